// round 5
// baseline (speedup 1.0000x reference)
#include <cuda_runtime.h>
#include <math.h>

// ANI AEV computer. M=32, A=48, S=4.
// Radial: 4 species x 16 ShfR = 64 ch. Angular: 10 sp-pairs x 4 ShfA x 8 ShfZ = 320 ch.
// Output (32, 48, 384) fp32.
//
// R1 (16.9us): lane-staggered shared atomics, 1 thread/pair.
// R4: per-warp private accumulator banks -> no cross-warp same-address atomic
//     contention; final 4-way reduction. Otherwise R1 structure.

#define MM 32
#define AA 48
#define SS 4
#define NSHFR 16
#define NSHFA 4
#define NSHFZ 8
#define RAD_SUB 16
#define ANG_SUB 32
#define NPAIRS_SP 10
#define OUT_PER_ATOM (SS * RAD_SUB + NPAIRS_SP * ANG_SUB)  // 384
#define RCR_F 5.2f
#define RCA_F 3.5f
#define NTHREADS 128
#define NWARPS (NTHREADS / 32)

__global__ __launch_bounds__(NTHREADS)
void aev_kernel(const float* __restrict__ coords,
                const float* __restrict__ EtaR,
                const float* __restrict__ ShfR,
                const float* __restrict__ EtaA,
                const float* __restrict__ Zeta,
                const float* __restrict__ ShfA,
                const float* __restrict__ ShfZ,
                const int*   __restrict__ species,
                float*       __restrict__ out)
{
    const int m    = blockIdx.x / AA;
    const int ci   = blockIdx.x % AA;
    const int tid  = threadIdx.x;
    const int lane = tid & 31;
    const int wid  = tid >> 5;

    __shared__ float sx[AA], sy[AA], sz[AA];
    __shared__ int   ssp[AA];
    __shared__ float acc[NWARPS][OUT_PER_ATOM];   // per-warp private banks
    __shared__ float shfR[NSHFR], shfA_s[NSHFA];
    __shared__ float cz2[NSHFZ], sz2[NSHFZ];      // 0.5*cos(ShfZ), 0.5*sin(ShfZ)
    __shared__ int   ptab[SS * SS];
    __shared__ float s_etaR, s_etaA, s_zeta;
    __shared__ int   nnb;
    __shared__ float nbd[AA], nbx[AA], nby[AA], nbz[AA], nbfc[AA];
    __shared__ int   nbsp[AA];

    if (tid < AA) {
        sx[tid]  = coords[(m * AA + tid) * 3 + 0];
        sy[tid]  = coords[(m * AA + tid) * 3 + 1];
        sz[tid]  = coords[(m * AA + tid) * 3 + 2];
        ssp[tid] = species[m * AA + tid];
    }
    if (tid < NSHFR) shfR[tid] = ShfR[tid];
    if (tid < NSHFA) shfA_s[tid] = ShfA[tid];
    if (tid < NSHFZ) {
        float s = ShfZ[tid];
        cz2[tid] = 0.5f * cosf(s);
        sz2[tid] = 0.5f * sinf(s);
    }
    if (tid < SS * SS) {
        int r = tid / SS, c = tid % SS;
        int lo = min(r, c), hi = max(r, c);
        ptab[tid] = lo * SS - (lo * (lo - 1)) / 2 + (hi - lo);
    }
    if (tid == 0) {
        s_etaR = EtaR[0];
        s_etaA = EtaA[0];
        s_zeta = Zeta[0];
        nnb = 0;
    }
    for (int c = tid; c < NWARPS * OUT_PER_ATOM; c += NTHREADS)
        ((float*)acc)[c] = 0.0f;
    __syncthreads();

    const float cxi = sx[ci], cyi = sy[ci], czi = sz[ci];
    float* const myacc = acc[wid];

    // ---- radial contributions + angular neighbor list build ----
    if (tid < AA && tid != ci) {
        const int j = tid;
        const float dx = sx[j] - cxi;
        const float dy = sy[j] - cyi;
        const float dz = sz[j] - czi;
        const float d  = sqrtf(dx * dx + dy * dy + dz * dz);

        if (d <= RCR_F) {
            const float fc   = 0.5f * __cosf(d * (float)(M_PI / 5.2)) + 0.5f;
            const float base = 0.25f * fc;
            const int   off  = ssp[j] * RAD_SUB;
            const float eR   = s_etaR;
            #pragma unroll
            for (int k = 0; k < NSHFR; k++) {
                const int t = (k + lane) & (NSHFR - 1);
                const float x = d - shfR[t];
                atomicAdd(&myacc[off + t], base * __expf(-eR * x * x));
            }
        }
        if (d <= RCA_F) {
            const int slot = atomicAdd(&nnb, 1);
            nbd[slot]  = d;
            nbx[slot]  = dx;
            nby[slot]  = dy;
            nbz[slot]  = dz;
            nbfc[slot] = 0.5f * __cosf(d * (float)(M_PI / 3.5)) + 0.5f;
            nbsp[slot] = ssp[j];
        }
    }
    __syncthreads();

    // ---- angular: one thread per neighbor pair ----
    const int n     = nnb;
    const int npair = n * (n - 1) / 2;
    const float etaA = s_etaA;
    const float zeta = s_zeta;
    const bool  z32  = (zeta == 32.0f);
    const int   rot_a = (lane >> 3) & 3;

    for (int p = tid; p < npair; p += NTHREADS) {
        // decode p -> (a, b), a < b   (linear scan; n <= 47)
        int a = 0, rem = p;
        while (rem >= n - 1 - a) { rem -= n - 1 - a; a++; }
        const int b = a + 1 + rem;

        const float d1 = nbd[a], d2 = nbd[b];
        const float inv = __fdividef(1.0f, fmaxf(d1, 1e-8f) * fmaxf(d2, 1e-8f));
        const float dot = nbx[a] * nbx[b] + nby[a] * nby[b] + nbz[a] * nbz[b];
        const float c   = 0.95f * dot * inv;
        const float sn  = sqrtf(fmaxf(1.0f - c * c, 0.0f));

        const float fcj2 = 2.0f * nbfc[a] * nbfc[b];
        const float dm   = 0.5f * (d1 + d2);
        const int  pidx  = ptab[nbsp[a] * SS + nbsp[b]];

        float* dst = &myacc[SS * RAD_SUB + pidx * ANG_SUB];

        // staggered (ia, iz): intra-warp conflict-free; cross-warp contention
        // is impossible now (private banks).
        #pragma unroll
        for (int ja = 0; ja < NSHFA; ja++) {
            const int ia = (ja + rot_a) & (NSHFA - 1);
            const float x  = dm - shfA_s[ia];
            const float f2 = __expf(-etaA * x * x) * fcj2;
            #pragma unroll
            for (int jz = 0; jz < NSHFZ; jz++) {
                const int iz = (jz + lane) & (NSHFZ - 1);
                // cos(arccos(c) - ShfZ) = c*cosZ + sqrt(1-c^2)*sinZ
                const float cz = fmaf(c, cz2[iz], fmaf(sn, sz2[iz], 0.5f));
                float f1;
                if (z32) {
                    float t = cz * cz;  // ^2
                    t *= t;             // ^4
                    t *= t;             // ^8
                    t *= t;             // ^16
                    t *= t;             // ^32
                    f1 = t;
                } else {
                    f1 = __powf(cz, zeta);
                }
                atomicAdd(&dst[ia * NSHFZ + iz], f1 * f2);
            }
        }
    }
    __syncthreads();

    // ---- reduce the 4 warp banks and write out ----
    float* o = out + (size_t)(m * AA + ci) * OUT_PER_ATOM;
    for (int c = tid; c < OUT_PER_ATOM; c += NTHREADS) {
        float v = acc[0][c] + acc[1][c] + acc[2][c] + acc[3][c];
        o[c] = v;
    }
}

extern "C" void kernel_launch(void* const* d_in, const int* in_sizes, int n_in,
                              void* d_out, int out_size)
{
    const float* coords  = (const float*)d_in[0];
    const float* EtaR    = (const float*)d_in[1];
    const float* ShfR    = (const float*)d_in[2];
    const float* EtaA    = (const float*)d_in[3];
    const float* Zeta    = (const float*)d_in[4];
    const float* ShfA    = (const float*)d_in[5];
    const float* ShfZ    = (const float*)d_in[6];
    const int*   species = (const int*)d_in[7];
    float* out = (float*)d_out;

    aev_kernel<<<MM * AA, NTHREADS>>>(coords, EtaR, ShfR, EtaA, Zeta,
                                      ShfA, ShfZ, species, out);
}

// round 6
// speedup vs baseline: 1.0663x; 1.0663x over previous
#include <cuda_runtime.h>
#include <math.h>

// ANI AEV computer. M=32, A=48, S=4.
// Radial: 4 species x 16 ShfR = 64 ch. Angular: 10 sp-pairs x 4 ShfA x 8 ShfZ = 320 ch.
// Output (32, 48, 384) fp32.
//
// R1 (16.9us): lane-staggered shared atomics, 1 thread/pair, block=(m,ci).
// R5: grid split 2x by ShfA-half: block (m,ci,h) handles channels ia in {2h,2h+1}.
//     Doubles exposed parallelism (machine was occupancy-starved at 196K threads),
//     duplicates only the cheap per-pair geometry. Disjoint output channels ->
//     no global atomics.

#define MM 32
#define AA 48
#define SS 4
#define NSHFR 16
#define NSHFA 4
#define NSHFZ 8
#define RAD_SUB 16
#define ANG_SUB 32
#define NPAIRS_SP 10
#define OUT_PER_ATOM (SS * RAD_SUB + NPAIRS_SP * ANG_SUB)  // 384
#define RCR_F 5.2f
#define RCA_F 3.5f
#define NTHREADS 128

__global__ __launch_bounds__(NTHREADS)
void aev_kernel(const float* __restrict__ coords,
                const float* __restrict__ EtaR,
                const float* __restrict__ ShfR,
                const float* __restrict__ EtaA,
                const float* __restrict__ Zeta,
                const float* __restrict__ ShfA,
                const float* __restrict__ ShfZ,
                const int*   __restrict__ species,
                float*       __restrict__ out)
{
    const int m    = blockIdx.x / AA;
    const int ci   = blockIdx.x % AA;
    const int h    = blockIdx.y;          // ShfA half: handles ia in {2h, 2h+1}
    const int tid  = threadIdx.x;
    const int lane = tid & 31;

    __shared__ float sx[AA], sy[AA], sz[AA];
    __shared__ int   ssp[AA];
    __shared__ float acc[OUT_PER_ATOM];
    __shared__ float shfR[NSHFR], shfA_s[NSHFA];
    __shared__ float cz2[NSHFZ], sz2[NSHFZ];    // 0.5*cos(ShfZ), 0.5*sin(ShfZ)
    __shared__ int   ptab[SS * SS];
    __shared__ float s_etaR, s_etaA, s_zeta;
    __shared__ int   nnb;
    __shared__ float nbd[AA], nbx[AA], nby[AA], nbz[AA], nbfc[AA];
    __shared__ int   nbsp[AA];

    if (tid < AA) {
        sx[tid]  = coords[(m * AA + tid) * 3 + 0];
        sy[tid]  = coords[(m * AA + tid) * 3 + 1];
        sz[tid]  = coords[(m * AA + tid) * 3 + 2];
        ssp[tid] = species[m * AA + tid];
    }
    if (tid < NSHFR) shfR[tid] = ShfR[tid];
    if (tid < NSHFA) shfA_s[tid] = ShfA[tid];
    if (tid < NSHFZ) {
        float s = ShfZ[tid];
        cz2[tid] = 0.5f * cosf(s);
        sz2[tid] = 0.5f * sinf(s);
    }
    if (tid < SS * SS) {
        int r = tid / SS, c = tid % SS;
        int lo = min(r, c), hi = max(r, c);
        ptab[tid] = lo * SS - (lo * (lo - 1)) / 2 + (hi - lo);
    }
    if (tid == 0) {
        s_etaR = EtaR[0];
        s_etaA = EtaA[0];
        s_zeta = Zeta[0];
        nnb = 0;
    }
    for (int c = tid; c < OUT_PER_ATOM; c += NTHREADS) acc[c] = 0.0f;
    __syncthreads();

    const float cxi = sx[ci], cyi = sy[ci], czi = sz[ci];

    // ---- radial (split 0 only) + angular neighbor list build (both) ----
    if (tid < AA && tid != ci) {
        const int j = tid;
        const float dx = sx[j] - cxi;
        const float dy = sy[j] - cyi;
        const float dz = sz[j] - czi;
        const float d  = sqrtf(dx * dx + dy * dy + dz * dz);

        if (h == 0 && d <= RCR_F) {
            const float fc   = 0.5f * __cosf(d * (float)(M_PI / 5.2)) + 0.5f;
            const float base = 0.25f * fc;
            const int   off  = ssp[j] * RAD_SUB;
            const float eR   = s_etaR;
            #pragma unroll
            for (int k = 0; k < NSHFR; k++) {
                const int t = (k + lane) & (NSHFR - 1);
                const float x = d - shfR[t];
                atomicAdd(&acc[off + t], base * __expf(-eR * x * x));
            }
        }
        if (d <= RCA_F) {
            const int slot = atomicAdd(&nnb, 1);
            nbd[slot]  = d;
            nbx[slot]  = dx;
            nby[slot]  = dy;
            nbz[slot]  = dz;
            nbfc[slot] = 0.5f * __cosf(d * (float)(M_PI / 3.5)) + 0.5f;
            nbsp[slot] = ssp[j];
        }
    }
    __syncthreads();

    // ---- angular: one thread per neighbor pair, 2 ShfA values per block ----
    const int n     = nnb;
    const int npair = n * (n - 1) / 2;
    const float etaA = s_etaA;
    const float zeta = s_zeta;
    const bool  z32  = (zeta == 32.0f);
    const int   rot_a = (lane >> 3) & 1;
    const int   ia0   = 2 * h;

    for (int p = tid; p < npair; p += NTHREADS) {
        // decode p -> (a, b), a < b   (linear scan; n <= 47)
        int a = 0, rem = p;
        while (rem >= n - 1 - a) { rem -= n - 1 - a; a++; }
        const int b = a + 1 + rem;

        const float d1 = nbd[a], d2 = nbd[b];
        const float inv = __fdividef(1.0f, fmaxf(d1, 1e-8f) * fmaxf(d2, 1e-8f));
        const float dot = nbx[a] * nbx[b] + nby[a] * nby[b] + nbz[a] * nbz[b];
        const float c   = 0.95f * dot * inv;
        const float sn  = sqrtf(fmaxf(1.0f - c * c, 0.0f));

        const float fcj2 = 2.0f * nbfc[a] * nbfc[b];
        const float dm   = 0.5f * (d1 + d2);
        const int  pidx  = ptab[nbsp[a] * SS + nbsp[b]];

        float* dst = &acc[SS * RAD_SUB + pidx * ANG_SUB];

        #pragma unroll
        for (int ja = 0; ja < 2; ja++) {
            const int ia = ia0 + ((ja + rot_a) & 1);
            const float x  = dm - shfA_s[ia];
            const float f2 = __expf(-etaA * x * x) * fcj2;
            #pragma unroll
            for (int jz = 0; jz < NSHFZ; jz++) {
                const int iz = (jz + lane) & (NSHFZ - 1);
                // cos(arccos(c) - ShfZ) = c*cosZ + sqrt(1-c^2)*sinZ
                const float cz = fmaf(c, cz2[iz], fmaf(sn, sz2[iz], 0.5f));
                float f1;
                if (z32) {
                    float t = cz * cz;  // ^2
                    t *= t;             // ^4
                    t *= t;             // ^8
                    t *= t;             // ^16
                    t *= t;             // ^32
                    f1 = t;
                } else {
                    f1 = __powf(cz, zeta);
                }
                atomicAdd(&dst[ia * NSHFZ + iz], f1 * f2);
            }
        }
    }
    __syncthreads();

    // ---- write out: disjoint channel sets per split ----
    float* o = out + (size_t)(m * AA + ci) * OUT_PER_ATOM;
    if (h == 0) {
        for (int c = tid; c < SS * RAD_SUB; c += NTHREADS) o[c] = acc[c];
    }
    // angular half: for each pidx, ia in {2h, 2h+1} -> 10 * 16 = 160 channels
    for (int idx = tid; idx < NPAIRS_SP * 2 * NSHFZ; idx += NTHREADS) {
        const int pidx = idx >> 4;          // / 16
        const int r    = idx & 15;
        const int ch   = SS * RAD_SUB + pidx * ANG_SUB + (ia0 + (r >> 3)) * NSHFZ + (r & 7);
        o[ch] = acc[ch];
    }
}

extern "C" void kernel_launch(void* const* d_in, const int* in_sizes, int n_in,
                              void* d_out, int out_size)
{
    const float* coords  = (const float*)d_in[0];
    const float* EtaR    = (const float*)d_in[1];
    const float* ShfR    = (const float*)d_in[2];
    const float* EtaA    = (const float*)d_in[3];
    const float* Zeta    = (const float*)d_in[4];
    const float* ShfA    = (const float*)d_in[5];
    const float* ShfZ    = (const float*)d_in[6];
    const int*   species = (const int*)d_in[7];
    float* out = (float*)d_out;

    dim3 grid(MM * AA, 2);
    aev_kernel<<<grid, NTHREADS>>>(coords, EtaR, ShfR, EtaA, Zeta,
                                   ShfA, ShfZ, species, out);
}